// round 9
// baseline (speedup 1.0000x reference)
#include <cuda_runtime.h>
#include <cuda_bf16.h>

#define SEQ    32768
#define WD     512
#define HID    1024
#define NCTA   64          // total CTAs; each handles BOTH folds (shared weights)
#define NFOLD  2
#define ARPC   8           // a/p rows per CTA
#define TRPC   16          // t rows per CTA
#define THREADS 256

typedef unsigned long long ull;

// Packed tag-embedded exchange slots: (tag<<32)|value_bits, 8B stride.
__device__ ull g_aslot[NFOLD][WD];
__device__ ull g_uslot[NFOLD][HID];
__device__ ull g_pslot[NFOLD][WD];
__device__ unsigned int g_epoch_base;   // bumped once per launch by CTA 0

__device__ __forceinline__ ull ldr64(const ull* p) {
    ull v; asm volatile("ld.relaxed.gpu.global.b64 %0, [%1];" : "=l"(v) : "l"(p) : "memory");
    return v;
}
__device__ __forceinline__ void str64(ull* p, ull v) {
    asm volatile("st.relaxed.gpu.global.b64 [%0], %1;" :: "l"(p), "l"(v) : "memory");
}
__device__ __forceinline__ ull pack(unsigned tag, float v) {
    return ((ull)tag << 32) | (ull)__float_as_uint(v);
}

// Poll N slots concurrently (MLP=N per sweep) until each tag >= want.
template <int N>
__device__ __forceinline__ void poll_slots(const ull* const (&sl)[N], unsigned want, float (&out)[N]) {
    unsigned pending = (1u << N) - 1u;
    ull v[N];
    while (pending) {
        #pragma unroll
        for (int j = 0; j < N; ++j)
            if (pending & (1u << j)) v[j] = ldr64(sl[j]);
        #pragma unroll
        for (int j = 0; j < N; ++j)
            if (pending & (1u << j))
                if ((int)((unsigned)(v[j] >> 32) - want) >= 0) pending &= ~(1u << j);
    }
    #pragma unroll
    for (int j = 0; j < N; ++j) out[j] = __uint_as_float((unsigned)(v[j] & 0xffffffffu));
}

// tanh with ~1e-7 abs error: 1 - 2/(e^{2x}+1)
__device__ __forceinline__ float ftanh(float x) {
    float e = __expf(2.0f * x);
    return 1.0f - __fdividef(2.0f, e + 1.0f);
}
__device__ __forceinline__ float dot4(float4 w, float4 h) {
    return w.x*h.x + w.y*h.y + w.z*h.z + w.w*h.w;
}

struct Smem {
    float p_s[NFOLD][WD];       // 4 KB
    float x_s[NFOLD][2][WD];    // 8 KB (double-buffered x per fold)
    float a_s[NFOLD][WD];       // 4 KB
    float u_s[NFOLD][HID];      // 8 KB (fold 0 half reused in epilogue)
    float lgst[8];
};

__global__ void __launch_bounds__(THREADS, 1)
rnn_fold_kernel(const float* __restrict__ input,
                const float* __restrict__ input2,
                const float* __restrict__ W1g, const float* __restrict__ b1g,
                const float* __restrict__ W2g, const float* __restrict__ b2g,
                const float* __restrict__ W3g, const float* __restrict__ b3g,
                const float* __restrict__ W4g, const float* __restrict__ b4g,
                float* __restrict__ out)
{
    __shared__ Smem s;

    const int tid  = threadIdx.x;
    const int lane = tid & 31;
    const int warp = tid >> 5;        // 0..7
    const int k    = blockIdx.x;      // 0..63

    const int arow0 = k * ARPC;       // global a/p row base
    const int trow0 = k * TRPC;       // global t row base

    const int row16 = (warp << 1) | (lane >> 4);   // local t-row (0..15)
    const int lg16  = lane & 15;

    // ---------------- weights -> registers (SHARED by both folds) ----------------
    float4 w1reg[8], w2reg[8], w3reg[8];
    {
        const float4* w1row = reinterpret_cast<const float4*>(W1g + (size_t)(arow0 + warp) * HID);
        const float4* w3row = reinterpret_cast<const float4*>(W3g + (size_t)(arow0 + warp) * HID);
        #pragma unroll
        for (int q = 0; q < 8; ++q) {
            w1reg[q] = w1row[lane + 32 * q];
            w3reg[q] = w3row[lane + 32 * q];
        }
        const float4* w2row = reinterpret_cast<const float4*>(W2g + (size_t)(trow0 + row16) * WD);
        #pragma unroll
        for (int q = 0; q < 8; ++q) w2reg[q] = w2row[lg16 + 16 * q];
    }
    const float b1r = b1g[arow0 + warp];
    const float b3r = b3g[arow0 + warp];
    const float b2r = b2g[trow0 + row16];

    // initial vectors: p0 = x[0], x buffer 1 = x[1] (both folds)
    reinterpret_cast<float2*>(s.p_s[0])[tid]    = reinterpret_cast<const float2*>(input)[tid];
    reinterpret_cast<float2*>(s.x_s[0][1])[tid] = reinterpret_cast<const float2*>(input + WD)[tid];
    reinterpret_cast<float2*>(s.p_s[1])[tid]    = reinterpret_cast<const float2*>(input2)[tid];
    reinterpret_cast<float2*>(s.x_s[1][1])[tid] = reinterpret_cast<const float2*>(input2 + WD)[tid];

    unsigned int base;
    asm volatile("ld.relaxed.gpu.global.u32 %0, [%1];" : "=r"(base) : "l"(&g_epoch_base) : "memory");
    __syncthreads();

    // xacc for step 1 (per fold): per-lane partial of (W1 x-half) . x[1]
    float xacc0 = 0.0f, xacc1 = 0.0f;
    {
        const float4* x0 = reinterpret_cast<const float4*>(s.x_s[0][1]);
        const float4* x1 = reinterpret_cast<const float4*>(s.x_s[1][1]);
        #pragma unroll
        for (int q = 0; q < 4; ++q) {
            xacc0 += dot4(w1reg[4 + q], x0[lane + 32 * q]);
            xacc1 += dot4(w1reg[4 + q], x1[lane + 32 * q]);
        }
    }

    for (int i = 1; i < SEQ; ++i) {
        const int buf = i & 1;
        const unsigned t1 = base + 3u * (unsigned)(i - 1) + 1u;
        const bool hasx = (i + 1 < SEQ);

        // prefetch next x (both folds) into registers
        float2 xn0 = make_float2(0.f, 0.f), xn1 = make_float2(0.f, 0.f);
        if (hasx) {
            xn0 = __ldcg(reinterpret_cast<const float2*>(input  + (size_t)(i + 1) * WD) + tid);
            xn1 = __ldcg(reinterpret_cast<const float2*>(input2 + (size_t)(i + 1) * WD) + tid);
        }

        // ---- stage 1 fold0 then fold1: a-row = relu(W1p.p + xacc + b1) ----
        {
            const float4* pp = reinterpret_cast<const float4*>(s.p_s[0]);
            float acc = xacc0;
            #pragma unroll
            for (int q = 0; q < 4; ++q) acc += dot4(w1reg[q], pp[lane + 32 * q]);
            #pragma unroll
            for (int o = 16; o > 0; o >>= 1) acc += __shfl_xor_sync(0xffffffffu, acc, o);
            if (lane == 0)
                str64(&g_aslot[0][arow0 + warp], pack(t1, fmaxf(acc + b1r, 0.0f)));
        }
        {
            const float4* pp = reinterpret_cast<const float4*>(s.p_s[1]);
            float acc = xacc1;
            #pragma unroll
            for (int q = 0; q < 4; ++q) acc += dot4(w1reg[q], pp[lane + 32 * q]);
            #pragma unroll
            for (int o = 16; o > 0; o >>= 1) acc += __shfl_xor_sync(0xffffffffu, acc, o);
            if (lane == 0)
                str64(&g_aslot[1][arow0 + warp], pack(t1, fmaxf(acc + b1r, 0.0f)));
        }

        // stash next x into the other buffer (read only after later syncs)
        if (hasx) {
            reinterpret_cast<float2*>(s.x_s[0][buf ^ 1])[tid] = xn0;
            reinterpret_cast<float2*>(s.x_s[1][buf ^ 1])[tid] = xn1;
        }

        // ---- gather a fold0 ----
        {
            const ull* sl[2] = { &g_aslot[0][2 * tid], &g_aslot[0][2 * tid + 1] };
            float av[2];
            poll_slots(sl, t1, av);
            reinterpret_cast<float2*>(s.a_s[0])[tid] = make_float2(av[0], av[1]);
        }
        __syncthreads();

        // ---- stage 2 fold0: u-row = tanh(W2.a + b2) ----
        {
            const float4* aa = reinterpret_cast<const float4*>(s.a_s[0]);
            float acc = 0.f;
            #pragma unroll
            for (int q = 0; q < 8; ++q) acc += dot4(w2reg[q], aa[lg16 + 16 * q]);
            #pragma unroll
            for (int o = 8; o > 0; o >>= 1) acc += __shfl_xor_sync(0xffffffffu, acc, o);
            if (lg16 == 0)
                str64(&g_uslot[0][trow0 + row16], pack(t1 + 1u, ftanh(acc + b2r)));
        }

        // ---- gather a fold1 ----
        {
            const ull* sl[2] = { &g_aslot[1][2 * tid], &g_aslot[1][2 * tid + 1] };
            float av[2];
            poll_slots(sl, t1, av);
            reinterpret_cast<float2*>(s.a_s[1])[tid] = make_float2(av[0], av[1]);
        }
        __syncthreads();

        // ---- stage 2 fold1 ----
        {
            const float4* aa = reinterpret_cast<const float4*>(s.a_s[1]);
            float acc = 0.f;
            #pragma unroll
            for (int q = 0; q < 8; ++q) acc += dot4(w2reg[q], aa[lg16 + 16 * q]);
            #pragma unroll
            for (int o = 8; o > 0; o >>= 1) acc += __shfl_xor_sync(0xffffffffu, acc, o);
            if (lg16 == 0)
                str64(&g_uslot[1][trow0 + row16], pack(t1 + 1u, ftanh(acc + b2r)));
        }

        // xacc for NEXT step, both folds (shadow of the u-exchange)
        if (hasx) {
            const float4* x0 = reinterpret_cast<const float4*>(s.x_s[0][buf ^ 1]);
            const float4* x1 = reinterpret_cast<const float4*>(s.x_s[1][buf ^ 1]);
            float xa0 = 0.f, xa1 = 0.f;
            #pragma unroll
            for (int q = 0; q < 4; ++q) {
                xa0 += dot4(w1reg[4 + q], x0[lane + 32 * q]);
                xa1 += dot4(w1reg[4 + q], x1[lane + 32 * q]);
            }
            xacc0 = xa0; xacc1 = xa1;
        }

        // ---- gather u fold0 ----
        {
            const ull* sl[4] = { &g_uslot[0][2 * tid],       &g_uslot[0][2 * tid + 1],
                                 &g_uslot[0][512 + 2 * tid], &g_uslot[0][512 + 2 * tid + 1] };
            float uv[4];
            poll_slots(sl, t1 + 1u, uv);
            reinterpret_cast<float2*>(s.u_s[0])[tid]       = make_float2(uv[0], uv[1]);
            reinterpret_cast<float2*>(s.u_s[0] + 512)[tid] = make_float2(uv[2], uv[3]);
        }
        __syncthreads();

        // ---- stage 3 fold0: p-row = tanh(W3.u + b3) ----
        {
            const float4* uu = reinterpret_cast<const float4*>(s.u_s[0]);
            float accA = 0.f, accB = 0.f;
            #pragma unroll
            for (int q = 0; q < 4; ++q) accA += dot4(w3reg[q], uu[lane + 32 * q]);
            #pragma unroll
            for (int q = 4; q < 8; ++q) accB += dot4(w3reg[q], uu[lane + 32 * q]);
            float acc = accA + accB;
            #pragma unroll
            for (int o = 16; o > 0; o >>= 1) acc += __shfl_xor_sync(0xffffffffu, acc, o);
            if (lane == 0)
                str64(&g_pslot[0][arow0 + warp], pack(t1 + 2u, ftanh(acc + b3r)));
        }

        // ---- gather u fold1 ----
        {
            const ull* sl[4] = { &g_uslot[1][2 * tid],       &g_uslot[1][2 * tid + 1],
                                 &g_uslot[1][512 + 2 * tid], &g_uslot[1][512 + 2 * tid + 1] };
            float uv[4];
            poll_slots(sl, t1 + 1u, uv);
            reinterpret_cast<float2*>(s.u_s[1])[tid]       = make_float2(uv[0], uv[1]);
            reinterpret_cast<float2*>(s.u_s[1] + 512)[tid] = make_float2(uv[2], uv[3]);
        }
        __syncthreads();

        // ---- stage 3 fold1 ----
        {
            const float4* uu = reinterpret_cast<const float4*>(s.u_s[1]);
            float accA = 0.f, accB = 0.f;
            #pragma unroll
            for (int q = 0; q < 4; ++q) accA += dot4(w3reg[q], uu[lane + 32 * q]);
            #pragma unroll
            for (int q = 4; q < 8; ++q) accB += dot4(w3reg[q], uu[lane + 32 * q]);
            float acc = accA + accB;
            #pragma unroll
            for (int o = 16; o > 0; o >>= 1) acc += __shfl_xor_sync(0xffffffffu, acc, o);
            if (lane == 0)
                str64(&g_pslot[1][arow0 + warp], pack(t1 + 2u, ftanh(acc + b3r)));
        }

        // ---- gather p (both folds) ----
        if (i < SEQ - 1) {
            {
                const ull* sl[2] = { &g_pslot[0][2 * tid], &g_pslot[0][2 * tid + 1] };
                float pv[2];
                poll_slots(sl, t1 + 2u, pv);
                reinterpret_cast<float2*>(s.p_s[0])[tid] = make_float2(pv[0], pv[1]);
            }
            {
                const ull* sl[2] = { &g_pslot[1][2 * tid], &g_pslot[1][2 * tid + 1] };
                float pv[2];
                poll_slots(sl, t1 + 2u, pv);
                reinterpret_cast<float2*>(s.p_s[1])[tid] = make_float2(pv[0], pv[1]);
            }
            __syncthreads();
        }
    }

    // ---------------- fused epilogue: CTA 0 gathers both folds' final p ----------------
    if (blockIdx.x == 0) {
        const unsigned tfin = base + 3u * (unsigned)(SEQ - 2) + 3u;
        {
            const ull* sl[4] = { &g_pslot[0][2 * tid], &g_pslot[0][2 * tid + 1],
                                 &g_pslot[1][2 * tid], &g_pslot[1][2 * tid + 1] };
            float pv[4];
            poll_slots(sl, tfin, pv);
            reinterpret_cast<float2*>(s.u_s[0])[tid]       = make_float2(pv[0], pv[1]);
            reinterpret_cast<float2*>(s.u_s[0] + 512)[tid] = make_float2(pv[2], pv[3]);
        }
        __syncthreads();

        if (warp < 5) {
            float acc = 0.0f;
            const float* w = W4g + warp * (2 * WD);
            for (int j = lane; j < 2 * WD; j += 32) acc += w[j] * s.u_s[0][j];
            #pragma unroll
            for (int o = 16; o > 0; o >>= 1) acc += __shfl_down_sync(0xffffffffu, acc, o);
            if (lane == 0) s.lgst[warp] = acc + b4g[warp];
        }
        __syncthreads();
        if (tid == 0) {
            float m = s.lgst[0];
            #pragma unroll
            for (int c = 1; c < 5; ++c) m = fmaxf(m, s.lgst[c]);
            float ssum = 0.0f;
            #pragma unroll
            for (int c = 0; c < 5; ++c) ssum += expf(s.lgst[c] - m);
            float lse = m + logf(ssum);
            #pragma unroll
            for (int c = 0; c < 5; ++c) out[c] = s.lgst[c] - lse;
            // bump epoch base for the next graph replay (3*SEQ > any tag used)
            unsigned nb = base + 3u * (unsigned)SEQ;
            asm volatile("st.relaxed.gpu.global.u32 [%0], %1;" :: "l"(&g_epoch_base), "r"(nb) : "memory");
        }
    }
}

extern "C" void kernel_launch(void* const* d_in, const int* in_sizes, int n_in,
                              void* d_out, int out_size)
{
    const float* input  = (const float*)d_in[0];
    const float* input2 = (const float*)d_in[1];
    const int off = (n_in >= 11) ? 3 : 2;
    const float* W1 = (const float*)d_in[off + 0];
    const float* b1 = (const float*)d_in[off + 1];
    const float* W2 = (const float*)d_in[off + 2];
    const float* b2 = (const float*)d_in[off + 3];
    const float* W3 = (const float*)d_in[off + 4];
    const float* b3 = (const float*)d_in[off + 5];
    const float* W4 = (const float*)d_in[off + 6];
    const float* b4 = (const float*)d_in[off + 7];

    rnn_fold_kernel<<<NCTA, THREADS>>>(
        input, input2, W1, b1, W2, b2, W3, b3, W4, b4, (float*)d_out);
}

// round 10
// speedup vs baseline: 1.5063x; 1.5063x over previous
#include <cuda_runtime.h>
#include <cuda_bf16.h>

#define SEQ    32768
#define WD     512
#define HID    1024
#define NCTA   64          // CTAs per fold
#define NFOLD  2
#define ARPC   8           // a/p rows per CTA
#define TRPC   16          // t rows per CTA
#define THREADS 256

typedef unsigned long long ull;

// Packed tag-embedded exchange slots: (tag<<32)|value_bits, 8B stride.
__device__ ull g_aslot[NFOLD][WD];
__device__ ull g_uslot[NFOLD][HID];
__device__ ull g_pslot[NFOLD][WD];
__device__ unsigned int g_epoch_base;   // bumped once per launch by CTA 0

__device__ __forceinline__ ull ldr64(const ull* p) {
    ull v; asm volatile("ld.relaxed.gpu.global.b64 %0, [%1];" : "=l"(v) : "l"(p) : "memory");
    return v;
}
__device__ __forceinline__ void str64(ull* p, ull v) {
    asm volatile("st.relaxed.gpu.global.b64 [%0], %1;" :: "l"(p), "l"(v) : "memory");
}
__device__ __forceinline__ ull pack(unsigned tag, float v) {
    return ((ull)tag << 32) | (ull)__float_as_uint(v);
}
__device__ __forceinline__ bool rdy(ull v, unsigned want) {
    return (int)((unsigned)(v >> 32) - want) >= 0;
}

// Software-pipelined poll: keep TWO sweeps in flight so detect quantization
// is ~RT/2 instead of ~RT. Values always taken from one coherent sweep.
template <int N>
__device__ __forceinline__ void poll_slots(const ull* const (&sl)[N], unsigned want, float (&out)[N]) {
    ull v[N], w[N];
    #pragma unroll
    for (int j = 0; j < N; ++j) v[j] = ldr64(sl[j]);       // sweep A in flight
    for (;;) {
        #pragma unroll
        for (int j = 0; j < N; ++j) w[j] = ldr64(sl[j]);   // sweep B in flight
        bool ok = true;
        #pragma unroll
        for (int j = 0; j < N; ++j) ok &= rdy(v[j], want); // consume sweep A
        if (ok) break;
        #pragma unroll
        for (int j = 0; j < N; ++j) v[j] = ldr64(sl[j]);   // sweep A' in flight
        ok = true;
        #pragma unroll
        for (int j = 0; j < N; ++j) ok &= rdy(w[j], want); // consume sweep B
        if (ok) {
            #pragma unroll
            for (int j = 0; j < N; ++j) v[j] = w[j];
            break;
        }
    }
    #pragma unroll
    for (int j = 0; j < N; ++j) out[j] = __uint_as_float((unsigned)(v[j] & 0xffffffffu));
}

// tanh with ~1e-7 abs error: 1 - 2/(e^{2x}+1)
__device__ __forceinline__ float ftanh(float x) {
    float e = __expf(2.0f * x);
    return 1.0f - __fdividef(2.0f, e + 1.0f);
}
__device__ __forceinline__ float dot4(float4 w, float4 h) {
    return w.x*h.x + w.y*h.y + w.z*h.z + w.w*h.w;
}

struct Smem {
    float p_s[WD];
    float x_s[2][WD];     // double-buffered x
    float a_s[WD];
    float u_s[HID];       // reused for [p0;p1] in the epilogue
    float lgst[8];
};

__global__ void __launch_bounds__(THREADS, 1)
rnn_fold_kernel(const float* __restrict__ input,
                const float* __restrict__ input2,
                const float* __restrict__ W1g, const float* __restrict__ b1g,
                const float* __restrict__ W2g, const float* __restrict__ b2g,
                const float* __restrict__ W3g, const float* __restrict__ b3g,
                const float* __restrict__ W4g, const float* __restrict__ b4g,
                float* __restrict__ out)
{
    __shared__ Smem s;

    const int tid  = threadIdx.x;
    const int lane = tid & 31;
    const int warp = tid >> 5;        // 0..7
    const int cta  = blockIdx.x;
    const int fold = cta / NCTA;
    const int k    = cta % NCTA;
    const float* xsrc = (fold == 0) ? input : input2;

    const int arow0 = k * ARPC;       // global a/p row base
    const int trow0 = k * TRPC;       // global t row base

    const int row16 = (warp << 1) | (lane >> 4);   // local t-row (0..15)
    const int lg16  = lane & 15;

    // ---------------- weights -> registers ----------------
    float4 w1reg[8], w2reg[8], w3reg[8];
    {
        const float4* w1row = reinterpret_cast<const float4*>(W1g + (size_t)(arow0 + warp) * HID);
        const float4* w3row = reinterpret_cast<const float4*>(W3g + (size_t)(arow0 + warp) * HID);
        #pragma unroll
        for (int q = 0; q < 8; ++q) {
            w1reg[q] = w1row[lane + 32 * q];
            w3reg[q] = w3row[lane + 32 * q];
        }
        const float4* w2row = reinterpret_cast<const float4*>(W2g + (size_t)(trow0 + row16) * WD);
        #pragma unroll
        for (int q = 0; q < 8; ++q) w2reg[q] = w2row[lg16 + 16 * q];
    }
    const float b1r = b1g[arow0 + warp];
    const float b3r = b3g[arow0 + warp];
    const float b2r = b2g[trow0 + row16];

    // initial vectors: p0 = x[0], x buffer 1 = x[1]
    reinterpret_cast<float2*>(s.p_s)[tid]    = reinterpret_cast<const float2*>(xsrc)[tid];
    reinterpret_cast<float2*>(s.x_s[1])[tid] = reinterpret_cast<const float2*>(xsrc + WD)[tid];

    unsigned int base;
    asm volatile("ld.relaxed.gpu.global.u32 %0, [%1];" : "=r"(base) : "l"(&g_epoch_base) : "memory");
    __syncthreads();

    // xacc for step 1: per-lane partial of (W1 x-half) . x[1]
    float xacc = 0.0f;
    {
        const float4* xx = reinterpret_cast<const float4*>(s.x_s[1]);
        #pragma unroll
        for (int q = 0; q < 4; ++q) xacc += dot4(w1reg[4 + q], xx[lane + 32 * q]);
    }

    for (int i = 1; i < SEQ; ++i) {
        const int buf = i & 1;
        const unsigned t1 = base + 3u * (unsigned)(i - 1) + 1u;
        const bool hasx = (i + 1 < SEQ);

        // prefetch next x into registers
        float2 xn = make_float2(0.f, 0.f);
        if (hasx) xn = __ldcg(reinterpret_cast<const float2*>(xsrc + (size_t)(i + 1) * WD) + tid);

        // ---- stage 1 (critical path = p-half only, 2 FFMA chains) ----
        {
            const float4* pp = reinterpret_cast<const float4*>(s.p_s);
            float accA = xacc, accB = 0.f;
            accA += dot4(w1reg[0], pp[lane]);
            accB += dot4(w1reg[1], pp[lane + 32]);
            accA += dot4(w1reg[2], pp[lane + 64]);
            accB += dot4(w1reg[3], pp[lane + 96]);
            float acc = accA + accB;
            #pragma unroll
            for (int o = 16; o > 0; o >>= 1) acc += __shfl_xor_sync(0xffffffffu, acc, o);
            if (lane == 0)
                str64(&g_aslot[fold][arow0 + warp], pack(t1, fmaxf(acc + b1r, 0.0f)));
        }

        // stash next x into the other buffer (read only after the a-gather sync)
        if (hasx) reinterpret_cast<float2*>(s.x_s[buf ^ 1])[tid] = xn;

        // ---- gather a: 2 packed slots / thread ----
        {
            const ull* sl[2] = { &g_aslot[fold][2 * tid], &g_aslot[fold][2 * tid + 1] };
            float av[2];
            poll_slots(sl, t1, av);
            reinterpret_cast<float2*>(s.a_s)[tid] = make_float2(av[0], av[1]);
        }
        __syncthreads();

        // ---- stage 2: u-row = tanh(W2.a + b2) (2 FFMA chains) ----
        {
            const float4* aa = reinterpret_cast<const float4*>(s.a_s);
            float accA = 0.f, accB = 0.f;
            #pragma unroll
            for (int q = 0; q < 8; q += 2) {
                accA += dot4(w2reg[q],     aa[lg16 + 16 * q]);
                accB += dot4(w2reg[q + 1], aa[lg16 + 16 * (q + 1)]);
            }
            float acc = accA + accB;
            #pragma unroll
            for (int o = 8; o > 0; o >>= 1) acc += __shfl_xor_sync(0xffffffffu, acc, o);
            if (lg16 == 0)
                str64(&g_uslot[fold][trow0 + row16], pack(t1 + 1u, ftanh(acc + b2r)));
        }

        // xacc for NEXT step (shadow of the u-exchange), from the freshly stashed buffer
        if (hasx) {
            const float4* xx = reinterpret_cast<const float4*>(s.x_s[buf ^ 1]);
            float xa = 0.f, xb = 0.f;
            xa += dot4(w1reg[4], xx[lane]);
            xb += dot4(w1reg[5], xx[lane + 32]);
            xa += dot4(w1reg[6], xx[lane + 64]);
            xb += dot4(w1reg[7], xx[lane + 96]);
            xacc = xa + xb;
        }

        // ---- gather u: 4 packed slots / thread ----
        {
            const ull* sl[4] = { &g_uslot[fold][2 * tid],       &g_uslot[fold][2 * tid + 1],
                                 &g_uslot[fold][512 + 2 * tid], &g_uslot[fold][512 + 2 * tid + 1] };
            float uv[4];
            poll_slots(sl, t1 + 1u, uv);
            reinterpret_cast<float2*>(s.u_s)[tid]       = make_float2(uv[0], uv[1]);
            reinterpret_cast<float2*>(s.u_s + 512)[tid] = make_float2(uv[2], uv[3]);
        }
        __syncthreads();

        // ---- stage 3: p-row = tanh(W3.u + b3) (2 FFMA chains) ----
        {
            const float4* uu = reinterpret_cast<const float4*>(s.u_s);
            float accA = 0.f, accB = 0.f;
            #pragma unroll
            for (int q = 0; q < 8; q += 2) {
                accA += dot4(w3reg[q],     uu[lane + 32 * q]);
                accB += dot4(w3reg[q + 1], uu[lane + 32 * (q + 1)]);
            }
            float acc = accA + accB;
            #pragma unroll
            for (int o = 16; o > 0; o >>= 1) acc += __shfl_xor_sync(0xffffffffu, acc, o);
            if (lane == 0)
                str64(&g_pslot[fold][arow0 + warp], pack(t1 + 2u, ftanh(acc + b3r)));
        }

        // ---- gather p: 2 packed slots / thread ----
        if (i < SEQ - 1) {
            const ull* sl[2] = { &g_pslot[fold][2 * tid], &g_pslot[fold][2 * tid + 1] };
            float pv[2];
            poll_slots(sl, t1 + 2u, pv);
            reinterpret_cast<float2*>(s.p_s)[tid] = make_float2(pv[0], pv[1]);
            __syncthreads();
        }
    }

    // ---------------- fused epilogue: CTA 0 gathers both folds' final p ----------------
    if (cta == 0) {
        const unsigned tfin = base + 3u * (unsigned)(SEQ - 2) + 3u;
        {
            const ull* sl[4] = { &g_pslot[0][2 * tid], &g_pslot[0][2 * tid + 1],
                                 &g_pslot[1][2 * tid], &g_pslot[1][2 * tid + 1] };
            float pv[4];
            poll_slots(sl, tfin, pv);
            reinterpret_cast<float2*>(s.u_s)[tid]       = make_float2(pv[0], pv[1]);
            reinterpret_cast<float2*>(s.u_s + 512)[tid] = make_float2(pv[2], pv[3]);
        }
        __syncthreads();

        if (warp < 5) {
            float acc = 0.0f;
            const float* w = W4g + warp * (2 * WD);
            for (int j = lane; j < 2 * WD; j += 32) acc += w[j] * s.u_s[j];
            #pragma unroll
            for (int o = 16; o > 0; o >>= 1) acc += __shfl_down_sync(0xffffffffu, acc, o);
            if (lane == 0) s.lgst[warp] = acc + b4g[warp];
        }
        __syncthreads();
        if (tid == 0) {
            float m = s.lgst[0];
            #pragma unroll
            for (int c = 1; c < 5; ++c) m = fmaxf(m, s.lgst[c]);
            float ssum = 0.0f;
            #pragma unroll
            for (int c = 0; c < 5; ++c) ssum += expf(s.lgst[c] - m);
            float lse = m + logf(ssum);
            #pragma unroll
            for (int c = 0; c < 5; ++c) out[c] = s.lgst[c] - lse;
            // bump epoch base for the next graph replay (3*SEQ > any tag used)
            unsigned nb = base + 3u * (unsigned)SEQ;
            asm volatile("st.relaxed.gpu.global.u32 [%0], %1;" :: "l"(&g_epoch_base), "r"(nb) : "memory");
        }
    }
}

extern "C" void kernel_launch(void* const* d_in, const int* in_sizes, int n_in,
                              void* d_out, int out_size)
{
    const float* input  = (const float*)d_in[0];
    const float* input2 = (const float*)d_in[1];
    const int off = (n_in >= 11) ? 3 : 2;
    const float* W1 = (const float*)d_in[off + 0];
    const float* b1 = (const float*)d_in[off + 1];
    const float* W2 = (const float*)d_in[off + 2];
    const float* b2 = (const float*)d_in[off + 3];
    const float* W3 = (const float*)d_in[off + 4];
    const float* b3 = (const float*)d_in[off + 5];
    const float* W4 = (const float*)d_in[off + 6];
    const float* b4 = (const float*)d_in[off + 7];

    rnn_fold_kernel<<<NFOLD * NCTA, THREADS>>>(
        input, input2, W1, b1, W2, b2, W3, b3, W4, b4, (float*)d_out);
}

// round 12
// speedup vs baseline: 2.5952x; 1.7229x over previous
#include <cuda_runtime.h>
#include <cuda_bf16.h>

#define SEQ    32768
#define WD     512
#define HID    1024
#define NCTA   64          // CTAs per fold
#define NFOLD  2
#define ARPC   8           // a/p rows per CTA
#define TRPC   16          // t rows per CTA
#define THREADS 256

typedef unsigned long long ull;

// Packed tag-embedded exchange slots: (tag<<32)|value_bits, 8B stride.
__device__ ull g_aslot[NFOLD][WD];
__device__ ull g_uslot[NFOLD][HID];
__device__ ull g_pslot[NFOLD][WD];
__device__ unsigned int g_epoch_base;   // bumped once per launch by CTA 0

__device__ __forceinline__ ull ldr64(const ull* p) {
    ull v; asm volatile("ld.relaxed.gpu.global.b64 %0, [%1];" : "=l"(v) : "l"(p) : "memory");
    return v;
}
__device__ __forceinline__ void str64(ull* p, ull v) {
    asm volatile("st.relaxed.gpu.global.b64 [%0], %1;" :: "l"(p), "l"(v) : "memory");
}
__device__ __forceinline__ ull pack(unsigned tag, float v) {
    return ((ull)tag << 32) | (ull)__float_as_uint(v);
}

// R8 poll: ONE dependent sweep in flight (minimum L2 poll traffic).
template <int N>
__device__ __forceinline__ void poll_slots(const ull* const (&sl)[N], unsigned want, float (&out)[N]) {
    unsigned pending = (1u << N) - 1u;
    ull v[N];
    while (pending) {
        #pragma unroll
        for (int j = 0; j < N; ++j)
            if (pending & (1u << j)) v[j] = ldr64(sl[j]);
        #pragma unroll
        for (int j = 0; j < N; ++j)
            if (pending & (1u << j))
                if ((int)((unsigned)(v[j] >> 32) - want) >= 0) pending &= ~(1u << j);
    }
    #pragma unroll
    for (int j = 0; j < N; ++j) out[j] = __uint_as_float((unsigned)(v[j] & 0xffffffffu));
}

// tanh with ~1e-7 abs error: 1 - 2/(e^{2x}+1)
__device__ __forceinline__ float ftanh(float x) {
    float e = __expf(2.0f * x);
    return 1.0f - __fdividef(2.0f, e + 1.0f);
}
__device__ __forceinline__ float dot4(float4 w, float4 h) {
    return w.x*h.x + w.y*h.y + w.z*h.z + w.w*h.w;
}

struct Smem {
    float p_s[WD];
    float x_s[2][WD];     // double-buffered x
    float a_s[WD];
    float u_s[HID];       // reused for [p0;p1] in the epilogue
    float lgst[8];
};

__global__ void __launch_bounds__(THREADS, 1)
rnn_fold_kernel(const float* __restrict__ input,
                const float* __restrict__ input2,
                const float* __restrict__ W1g, const float* __restrict__ b1g,
                const float* __restrict__ W2g, const float* __restrict__ b2g,
                const float* __restrict__ W3g, const float* __restrict__ b3g,
                const float* __restrict__ W4g, const float* __restrict__ b4g,
                float* __restrict__ out)
{
    __shared__ Smem s;

    const int tid  = threadIdx.x;
    const int lane = tid & 31;
    const int warp = tid >> 5;        // 0..7
    const int cta  = blockIdx.x;
    const int fold = cta / NCTA;
    const int k    = cta % NCTA;
    const float* xsrc = (fold == 0) ? input : input2;

    const int arow0 = k * ARPC;       // global a/p row base
    const int trow0 = k * TRPC;       // global t row base

    const int row16 = (warp << 1) | (lane >> 4);   // local t-row (0..15)
    const int lg16  = lane & 15;

    // ---------------- weights -> registers ----------------
    float4 w1reg[8], w2reg[8], w3reg[8];
    {
        const float4* w1row = reinterpret_cast<const float4*>(W1g + (size_t)(arow0 + warp) * HID);
        const float4* w3row = reinterpret_cast<const float4*>(W3g + (size_t)(arow0 + warp) * HID);
        #pragma unroll
        for (int q = 0; q < 8; ++q) {
            w1reg[q] = w1row[lane + 32 * q];
            w3reg[q] = w3row[lane + 32 * q];
        }
        const float4* w2row = reinterpret_cast<const float4*>(W2g + (size_t)(trow0 + row16) * WD);
        #pragma unroll
        for (int q = 0; q < 8; ++q) w2reg[q] = w2row[lg16 + 16 * q];
    }
    const float b1r = b1g[arow0 + warp];
    const float b3r = b3g[arow0 + warp];
    const float b2r = b2g[trow0 + row16];

    // initial vectors: p0 = x[0], x buffer 1 = x[1]
    reinterpret_cast<float2*>(s.p_s)[tid]    = reinterpret_cast<const float2*>(xsrc)[tid];
    reinterpret_cast<float2*>(s.x_s[1])[tid] = reinterpret_cast<const float2*>(xsrc + WD)[tid];

    unsigned int base;
    asm volatile("ld.relaxed.gpu.global.u32 %0, [%1];" : "=r"(base) : "l"(&g_epoch_base) : "memory");
    __syncthreads();

    // xacc for step 1: per-lane partial of (W1 x-half) . x[1]
    float xacc = 0.0f;
    {
        const float4* xx = reinterpret_cast<const float4*>(s.x_s[1]);
        #pragma unroll
        for (int q = 0; q < 4; ++q) xacc += dot4(w1reg[4 + q], xx[lane + 32 * q]);
    }

    for (int i = 1; i < SEQ; ++i) {
        const int buf = i & 1;
        const unsigned t1 = base + 3u * (unsigned)(i - 1) + 1u;
        const bool hasx = (i + 1 < SEQ);

        // prefetch next x into registers
        float2 xn = make_float2(0.f, 0.f);
        if (hasx) xn = __ldcg(reinterpret_cast<const float2*>(xsrc + (size_t)(i + 1) * WD) + tid);

        // ---- stage 1 (critical path = p-half only, 2 FFMA chains) ----
        {
            const float4* pp = reinterpret_cast<const float4*>(s.p_s);
            float accA = xacc, accB = 0.f;
            accA += dot4(w1reg[0], pp[lane]);
            accB += dot4(w1reg[1], pp[lane + 32]);
            accA += dot4(w1reg[2], pp[lane + 64]);
            accB += dot4(w1reg[3], pp[lane + 96]);
            float acc = accA + accB;
            #pragma unroll
            for (int o = 16; o > 0; o >>= 1) acc += __shfl_xor_sync(0xffffffffu, acc, o);
            if (lane == 0)
                str64(&g_aslot[fold][arow0 + warp], pack(t1, fmaxf(acc + b1r, 0.0f)));
        }

        // stash next x into the other buffer (read only after the a-gather sync)
        if (hasx) reinterpret_cast<float2*>(s.x_s[buf ^ 1])[tid] = xn;

        // ---- gather a: 2 packed slots / thread ----
        {
            const ull* sl[2] = { &g_aslot[fold][2 * tid], &g_aslot[fold][2 * tid + 1] };
            float av[2];
            poll_slots(sl, t1, av);
            reinterpret_cast<float2*>(s.a_s)[tid] = make_float2(av[0], av[1]);
        }
        __syncthreads();

        // ---- stage 2: u-row = tanh(W2.a + b2) (2 FFMA chains) ----
        {
            const float4* aa = reinterpret_cast<const float4*>(s.a_s);
            float accA = 0.f, accB = 0.f;
            #pragma unroll
            for (int q = 0; q < 8; q += 2) {
                accA += dot4(w2reg[q],     aa[lg16 + 16 * q]);
                accB += dot4(w2reg[q + 1], aa[lg16 + 16 * (q + 1)]);
            }
            float acc = accA + accB;
            #pragma unroll
            for (int o = 8; o > 0; o >>= 1) acc += __shfl_xor_sync(0xffffffffu, acc, o);
            if (lg16 == 0)
                str64(&g_uslot[fold][trow0 + row16], pack(t1 + 1u, ftanh(acc + b2r)));
        }

        // xacc for NEXT step (shadow of the u-exchange), from the freshly stashed buffer
        if (hasx) {
            const float4* xx = reinterpret_cast<const float4*>(s.x_s[buf ^ 1]);
            float xa = 0.f, xb = 0.f;
            xa += dot4(w1reg[4], xx[lane]);
            xb += dot4(w1reg[5], xx[lane + 32]);
            xa += dot4(w1reg[6], xx[lane + 64]);
            xb += dot4(w1reg[7], xx[lane + 96]);
            xacc = xa + xb;
        }

        // ---- gather u: 4 packed slots / thread ----
        {
            const ull* sl[4] = { &g_uslot[fold][2 * tid],       &g_uslot[fold][2 * tid + 1],
                                 &g_uslot[fold][512 + 2 * tid], &g_uslot[fold][512 + 2 * tid + 1] };
            float uv[4];
            poll_slots(sl, t1 + 1u, uv);
            reinterpret_cast<float2*>(s.u_s)[tid]       = make_float2(uv[0], uv[1]);
            reinterpret_cast<float2*>(s.u_s + 512)[tid] = make_float2(uv[2], uv[3]);
        }
        __syncthreads();

        // ---- stage 3: p-row = tanh(W3.u + b3) (2 FFMA chains) ----
        {
            const float4* uu = reinterpret_cast<const float4*>(s.u_s);
            float accA = 0.f, accB = 0.f;
            #pragma unroll
            for (int q = 0; q < 8; q += 2) {
                accA += dot4(w3reg[q],     uu[lane + 32 * q]);
                accB += dot4(w3reg[q + 1], uu[lane + 32 * (q + 1)]);
            }
            float acc = accA + accB;
            #pragma unroll
            for (int o = 16; o > 0; o >>= 1) acc += __shfl_xor_sync(0xffffffffu, acc, o);
            if (lane == 0)
                str64(&g_pslot[fold][arow0 + warp], pack(t1 + 2u, ftanh(acc + b3r)));
        }

        // ---- gather p: 2 packed slots / thread ----
        if (i < SEQ - 1) {
            const ull* sl[2] = { &g_pslot[fold][2 * tid], &g_pslot[fold][2 * tid + 1] };
            float pv[2];
            poll_slots(sl, t1 + 2u, pv);
            reinterpret_cast<float2*>(s.p_s)[tid] = make_float2(pv[0], pv[1]);
            __syncthreads();
        }
    }

    // ---------------- fused epilogue: CTA 0 gathers both folds' final p ----------------
    if (cta == 0) {
        const unsigned tfin = base + 3u * (unsigned)(SEQ - 2) + 3u;
        {
            const ull* sl[4] = { &g_pslot[0][2 * tid], &g_pslot[0][2 * tid + 1],
                                 &g_pslot[1][2 * tid], &g_pslot[1][2 * tid + 1] };
            float pv[4];
            poll_slots(sl, tfin, pv);
            reinterpret_cast<float2*>(s.u_s)[tid]       = make_float2(pv[0], pv[1]);
            reinterpret_cast<float2*>(s.u_s + 512)[tid] = make_float2(pv[2], pv[3]);
        }
        __syncthreads();

        if (warp < 5) {
            float acc = 0.0f;
            const float* w = W4g + warp * (2 * WD);
            for (int j = lane; j < 2 * WD; j += 32) acc += w[j] * s.u_s[j];
            #pragma unroll
            for (int o = 16; o > 0; o >>= 1) acc += __shfl_down_sync(0xffffffffu, acc, o);
            if (lane == 0) s.lgst[warp] = acc + b4g[warp];
        }
        __syncthreads();
        if (tid == 0) {
            float m = s.lgst[0];
            #pragma unroll
            for (int c = 1; c < 5; ++c) m = fmaxf(m, s.lgst[c]);
            float ssum = 0.0f;
            #pragma unroll
            for (int c = 0; c < 5; ++c) ssum += expf(s.lgst[c] - m);
            float lse = m + logf(ssum);
            #pragma unroll
            for (int c = 0; c < 5; ++c) out[c] = s.lgst[c] - lse;
            // bump epoch base for the next graph replay (3*SEQ > any tag used)
            unsigned nb = base + 3u * (unsigned)SEQ;
            asm volatile("st.relaxed.gpu.global.u32 [%0], %1;" :: "l"(&g_epoch_base), "r"(nb) : "memory");
        }
    }
}

extern "C" void kernel_launch(void* const* d_in, const int* in_sizes, int n_in,
                              void* d_out, int out_size)
{
    const float* input  = (const float*)d_in[0];
    const float* input2 = (const float*)d_in[1];
    const int off = (n_in >= 11) ? 3 : 2;
    const float* W1 = (const float*)d_in[off + 0];
    const float* b1 = (const float*)d_in[off + 1];
    const float* W2 = (const float*)d_in[off + 2];
    const float* b2 = (const float*)d_in[off + 3];
    const float* W3 = (const float*)d_in[off + 4];
    const float* b3 = (const float*)d_in[off + 5];
    const float* W4 = (const float*)d_in[off + 6];
    const float* b4 = (const float*)d_in[off + 7];

    rnn_fold_kernel<<<NFOLD * NCTA, THREADS>>>(
        input, input2, W1, b1, W2, b2, W3, b3, W4, b4, (float*)d_out);
}